// round 3
// baseline (speedup 1.0000x reference)
#include <cuda_runtime.h>

typedef unsigned long long ull;

#define N_NODES 100000
#define N_EDGES 1600000
#define HID 64
#define EDIM 16
#define IN1 144   // 2*HID + EDIM

// scatter-add scratch (static device global: allocation-free, zero-initialized,
// and node_kernel re-zeroes it after reading -> every launch sees zeros)
__device__ float g_agg[(size_t)N_NODES * HID];

// ---------- packed f32x2 helpers ----------
__device__ __forceinline__ ull pack2(float v) {
    ull r;
    asm("mov.b64 %0, {%1, %1};" : "=l"(r) : "f"(v));
    return r;
}
__device__ __forceinline__ ull pack_pair(float lo, float hi) {
    ull r;
    asm("mov.b64 %0, {%1, %2};" : "=l"(r) : "f"(lo), "f"(hi));
    return r;
}
__device__ __forceinline__ void unpack2(ull v, float& lo, float& hi) {
    asm("mov.b64 {%0, %1}, %2;" : "=f"(lo), "=f"(hi) : "l"(v));
}
__device__ __forceinline__ void ffma2(ull& d, ull a, ull b) {
    asm("fma.rn.f32x2 %0, %1, %2, %0;" : "+l"(d) : "l"(a), "l"(b));
}
__device__ __forceinline__ float silu_f(float v) {
    return __fdividef(v, 1.0f + __expf(-v));
}
__device__ __forceinline__ void red_add4(float* p, float a, float b, float c, float d) {
    asm volatile("red.global.add.v4.f32 [%0], {%1, %2, %3, %4};"
                 :: "l"(p), "f"(a), "f"(b), "f"(c), "f"(d) : "memory");
}

// one input value vs full 64-wide weight row (32 packed FMAs, broadcast LDS)
__device__ __forceinline__ void accum1(ull* acc, ull m, const float* row) {
    const ulonglong2* r = (const ulonglong2*)row;
    #pragma unroll
    for (int j = 0; j < 16; j++) {
        ulonglong2 w = r[j];   // uniform addr across warp -> broadcast LDS.128
        ffma2(acc[2 * j],     m, w.x);
        ffma2(acc[2 * j + 1], m, w.y);
    }
}
// one input value vs a 32-wide half of a weight row (16 packed FMAs)
__device__ __forceinline__ void accum_half(ull* acc, ull m, const float* row) {
    const ulonglong2* r = (const ulonglong2*)row;
    #pragma unroll
    for (int j = 0; j < 8; j++) {
        ulonglong2 w = r[j];
        ffma2(acc[2 * j],     m, w.x);
        ffma2(acc[2 * j + 1], m, w.y);
    }
}
__device__ __forceinline__ void accum4(ull* acc, float4 v, const float* base) {
    accum1(acc, pack2(v.x), base);
    accum1(acc, pack2(v.y), base + HID);
    accum1(acc, pack2(v.z), base + 2 * HID);
    accum1(acc, pack2(v.w), base + 3 * HID);
}

// ---------- edge MLP + scatter ----------
#define EDGE_SMEM ((IN1 * HID + HID * HID + 2 * HID) * 4)  // 53760 B

__global__ void __launch_bounds__(128, 3) edge_kernel(
    const float* __restrict__ x, const int* __restrict__ ei,
    const float* __restrict__ ea,
    const float* __restrict__ W1, const float* __restrict__ b1,
    const float* __restrict__ W2, const float* __restrict__ b2)
{
    extern __shared__ float sm[];
    float* sW1 = sm;                          // 144*64
    float* sW2 = sm + IN1 * HID;              // 64*64
    float* sB1 = sm + IN1 * HID + HID * HID;  // 64
    float* sB2 = sB1 + HID;                   // 64

    for (int i = threadIdx.x; i < IN1 * HID / 4; i += blockDim.x)
        ((float4*)sW1)[i] = __ldg(((const float4*)W1) + i);
    for (int i = threadIdx.x; i < HID * HID / 4; i += blockDim.x)
        ((float4*)sW2)[i] = __ldg(((const float4*)W2) + i);
    if (threadIdx.x < HID)            sB1[threadIdx.x]       = b1[threadIdx.x];
    else if (threadIdx.x < 2 * HID)   sB2[threadIdx.x - HID] = b2[threadIdx.x - HID];
    __syncthreads();

    const int* srcp = ei;
    const int* dstp = ei + N_EDGES;

    for (int e = blockIdx.x * blockDim.x + threadIdx.x; e < N_EDGES;
         e += gridDim.x * blockDim.x) {
        int s = srcp[e], d = dstp[e];
        const float4* xs  = (const float4*)(x  + (size_t)s * HID);
        const float4* xd  = (const float4*)(x  + (size_t)d * HID);
        const float4* eap = (const float4*)(ea + (size_t)e * EDIM);

        // ---- layer 1: h_pre = W1^T m_in + b1 (packed pairs, prefetched gathers)
        ull acc[HID / 2];
        #pragma unroll
        for (int j = 0; j < HID / 2; j++) acc[j] = ((const ull*)sB1)[j];

        float4 cur = xs[0];
        #pragma unroll 1
        for (int k4 = 0; k4 < 16; k4++) {
            float4 nxt = (k4 < 15) ? xs[k4 + 1] : xd[0];
            accum4(acc, cur, sW1 + (4 * k4) * HID);
            cur = nxt;
        }
        #pragma unroll 1
        for (int k4 = 0; k4 < 16; k4++) {
            float4 nxt = (k4 < 15) ? xd[k4 + 1] : eap[0];
            accum4(acc, cur, sW1 + (64 + 4 * k4) * HID);
            cur = nxt;
        }
        #pragma unroll 1
        for (int k4 = 0; k4 < 4; k4++) {
            float4 nxt = (k4 < 3) ? eap[k4 + 1] : cur;
            accum4(acc, cur, sW1 + (128 + 4 * k4) * HID);
            cur = nxt;
        }

        // ---- silu in place on h (keeps only ONE 64-reg accumulator live)
        #pragma unroll
        for (int j = 0; j < HID / 2; j++) {
            float lo, hi;
            unpack2(acc[j], lo, hi);
            acc[j] = pack_pair(silu_f(lo), silu_f(hi));
        }

        // ---- layer 2 in two 32-output halves (acc2 = 32 regs, no spills)
        float* aggp = g_agg + (size_t)d * HID;
        #pragma unroll 1
        for (int h = 0; h < 2; h++) {
            const float* w2h = sW2 + h * 32;
            ull acc2[16];
            #pragma unroll
            for (int j = 0; j < 16; j++)
                acc2[j] = ((const ull*)sB2)[h * 16 + j];

            #pragma unroll 1
            for (int jp = 0; jp < HID / 2; jp++) {
                float lo, hi;
                unpack2(acc[jp], lo, hi);
                accum_half(acc2, pack2(lo), w2h + (2 * jp) * HID);
                accum_half(acc2, pack2(hi), w2h + (2 * jp + 1) * HID);
            }

            // silu + vectorized scatter-add of this half
            #pragma unroll
            for (int j = 0; j < 8; j++) {
                float a0, a1, a2, a3;
                unpack2(acc2[2 * j],     a0, a1);
                unpack2(acc2[2 * j + 1], a2, a3);
                red_add4(aggp + h * 32 + 4 * j,
                         silu_f(a0), silu_f(a1), silu_f(a2), silu_f(a3));
            }
        }
    }
}

// ---------- node MLP (also re-zeroes g_agg for the next launch) ----------
#define NODE_SMEM ((2 * HID * HID + HID) * 4)  // 33024 B

__global__ void __launch_bounds__(128) node_kernel(
    const float* __restrict__ x,
    const float* __restrict__ W3, const float* __restrict__ b3,
    float* __restrict__ out)
{
    extern __shared__ float sm[];
    float* sW3 = sm;                 // 128*64
    float* sB3 = sm + 2 * HID * HID; // 64

    for (int i = threadIdx.x; i < 2 * HID * HID / 4; i += blockDim.x)
        ((float4*)sW3)[i] = __ldg(((const float4*)W3) + i);
    if (threadIdx.x < HID) sB3[threadIdx.x] = b3[threadIdx.x];
    __syncthreads();

    int n = blockIdx.x * blockDim.x + threadIdx.x;
    if (n >= N_NODES) return;

    const float4* xr = (const float4*)(x + (size_t)n * HID);
    float4*       ar = (float4*)(g_agg + (size_t)n * HID);

    ull acc[HID / 2];
    #pragma unroll
    for (int j = 0; j < HID / 2; j++) acc[j] = ((const ull*)sB3)[j];

    #pragma unroll 1
    for (int k4 = 0; k4 < 16; k4++)
        accum4(acc, xr[k4], sW3 + (4 * k4) * HID);
    #pragma unroll 1
    for (int k4 = 0; k4 < 16; k4++) {
        float4 a = ar[k4];
        accum4(acc, a, sW3 + (64 + 4 * k4) * HID);
        ar[k4] = make_float4(0.f, 0.f, 0.f, 0.f);  // re-zero for next launch
    }

    float4* op = (float4*)(out + (size_t)n * HID);
    #pragma unroll
    for (int j = 0; j < 16; j++) {
        float a0, a1, a2, a3;
        unpack2(acc[2 * j],     a0, a1);
        unpack2(acc[2 * j + 1], a2, a3);
        op[j] = make_float4(silu_f(a0), silu_f(a1), silu_f(a2), silu_f(a3));
    }
}

extern "C" void kernel_launch(void* const* d_in, const int* in_sizes, int n_in,
                              void* d_out, int out_size) {
    const float* x   = (const float*)d_in[0];
    const int*   ei  = (const int*)  d_in[1];
    const float* ea  = (const float*)d_in[2];
    const float* W1  = (const float*)d_in[3];
    const float* b1  = (const float*)d_in[4];
    const float* W2  = (const float*)d_in[5];
    const float* b2  = (const float*)d_in[6];
    const float* W3  = (const float*)d_in[7];
    const float* b3  = (const float*)d_in[8];
    float* out = (float*)d_out;

    cudaFuncSetAttribute(edge_kernel, cudaFuncAttributeMaxDynamicSharedMemorySize, EDGE_SMEM);
    cudaFuncSetAttribute(node_kernel, cudaFuncAttributeMaxDynamicSharedMemorySize, NODE_SMEM);

    edge_kernel<<<444, 128, EDGE_SMEM>>>(x, ei, ea, W1, b1, W2, b2);

    int ngrid = (N_NODES + 127) / 128;
    node_kernel<<<ngrid, 128, NODE_SMEM>>>(x, W3, b3, out);
}

// round 4
// speedup vs baseline: 2.8546x; 2.8546x over previous
#include <cuda_runtime.h>

typedef unsigned long long ull;

#define N_NODES 100000
#define N_EDGES 1600000
#define HID 64
#define EDIM 16
#define IN1 144   // 2*HID + EDIM

// static device scratch (allocation-free). g_agg zero-init; re-zeroed by
// zero_agg_kernel at the END of each call so every call sees zeros.
__device__ float g_agg[(size_t)N_NODES * HID];
__device__ float g_ps [(size_t)N_NODES * HID];   // x @ W1[rows 0:64]   + b1
__device__ float g_pd [(size_t)N_NODES * HID];   // x @ W1[rows 64:128]

// ---------- packed f32x2 helpers ----------
__device__ __forceinline__ ull pack2(float v) {
    ull r; asm("mov.b64 %0, {%1, %1};" : "=l"(r) : "f"(v)); return r;
}
__device__ __forceinline__ ull pack_pair(float lo, float hi) {
    ull r; asm("mov.b64 %0, {%1, %2};" : "=l"(r) : "f"(lo), "f"(hi)); return r;
}
__device__ __forceinline__ void unpack2(ull v, float& lo, float& hi) {
    asm("mov.b64 {%0, %1}, %2;" : "=f"(lo), "=f"(hi) : "l"(v));
}
__device__ __forceinline__ void ffma2(ull& d, ull a, ull b) {
    asm("fma.rn.f32x2 %0, %1, %2, %0;" : "+l"(d) : "l"(a), "l"(b));
}
__device__ __forceinline__ void fadd2(ull& d, ull a) {
    asm("add.rn.f32x2 %0, %0, %1;" : "+l"(d) : "l"(a));
}
__device__ __forceinline__ float silu_f(float v) {
    return __fdividef(v, 1.0f + __expf(-v));
}
__device__ __forceinline__ void red_add4(float* p, float a, float b, float c, float d) {
    asm volatile("red.global.add.v4.f32 [%0], {%1, %2, %3, %4};"
                 :: "l"(p), "f"(a), "f"(b), "f"(c), "f"(d) : "memory");
}

// one input value vs 64-wide weight row (32 packed FMAs, broadcast LDS)
__device__ __forceinline__ void accum1(ull* acc, ull m, const float* row) {
    const ulonglong2* r = (const ulonglong2*)row;
    #pragma unroll
    for (int j = 0; j < 16; j++) {
        ulonglong2 w = r[j];
        ffma2(acc[2 * j],     m, w.x);
        ffma2(acc[2 * j + 1], m, w.y);
    }
}
// one input value vs a 32-wide half-row (16 packed FMAs)
__device__ __forceinline__ void accum_half(ull* acc, ull m, const float* row) {
    const ulonglong2* r = (const ulonglong2*)row;
    #pragma unroll
    for (int j = 0; j < 8; j++) {
        ulonglong2 w = r[j];
        ffma2(acc[2 * j],     m, w.x);
        ffma2(acc[2 * j + 1], m, w.y);
    }
}
__device__ __forceinline__ void accum4(ull* acc, float4 v, const float* base) {
    accum1(acc, pack2(v.x), base);
    accum1(acc, pack2(v.y), base + HID);
    accum1(acc, pack2(v.z), base + 2 * HID);
    accum1(acc, pack2(v.w), base + 3 * HID);
}

// ---------- 1) per-node projections ps/pd  ----------
#define PROJ_SMEM ((2 * HID * HID + HID) * 4)   // W1[0:128] rows + b1 = 33 KB

__global__ void __launch_bounds__(128, 4) proj_kernel(
    const float* __restrict__ x,
    const float* __restrict__ W1, const float* __restrict__ b1)
{
    extern __shared__ float sm[];
    float* sW = sm;                  // rows 0..127 of W1 (src part then dst part)
    float* sB = sm + 2 * HID * HID;

    for (int i = threadIdx.x; i < 2 * HID * HID / 4; i += blockDim.x)
        ((float4*)sW)[i] = __ldg(((const float4*)W1) + i);
    if (threadIdx.x < HID) sB[threadIdx.x] = b1[threadIdx.x];
    __syncthreads();

    int n = blockIdx.x * blockDim.x + threadIdx.x;
    if (n >= N_NODES) return;

    const float4* xr = (const float4*)(x + (size_t)n * HID);
    float4 xv[16];
    #pragma unroll
    for (int k = 0; k < 16; k++) xv[k] = xr[k];

    // ps = x @ W1s + b1
    {
        ull acc[HID / 2];
        #pragma unroll
        for (int j = 0; j < HID / 2; j++) acc[j] = ((const ull*)sB)[j];
        #pragma unroll 1
        for (int k4 = 0; k4 < 16; k4++)
            accum4(acc, xv[k4], sW + (4 * k4) * HID);
        ull* o = (ull*)(g_ps + (size_t)n * HID);
        #pragma unroll
        for (int j = 0; j < HID / 2; j++) o[j] = acc[j];
    }
    // pd = x @ W1d
    {
        ull acc[HID / 2];
        #pragma unroll
        for (int j = 0; j < HID / 2; j++) acc[j] = 0ULL;
        #pragma unroll 1
        for (int k4 = 0; k4 < 16; k4++)
            accum4(acc, xv[k4], sW + (64 + 4 * k4) * HID);
        ull* o = (ull*)(g_pd + (size_t)n * HID);
        #pragma unroll
        for (int j = 0; j < HID / 2; j++) o[j] = acc[j];
    }
}

// ---------- 2) edge MLP + scatter (uses ps/pd) ----------
#define EDGE_SMEM ((EDIM * HID + HID * HID + HID) * 4)   // W1e + W2 + b2 = 21 KB

__global__ void __launch_bounds__(128, 3) edge_kernel(
    const int* __restrict__ ei, const float* __restrict__ ea,
    const float* __restrict__ W1, const float* __restrict__ b2,
    const float* __restrict__ W2)
{
    extern __shared__ float sm[];
    float* sWe = sm;                       // W1 rows 128..143 (edge_attr part)
    float* sW2 = sm + EDIM * HID;          // 64*64
    float* sB2 = sW2 + HID * HID;          // 64

    const float* W1e = W1 + 128 * HID;
    for (int i = threadIdx.x; i < EDIM * HID / 4; i += blockDim.x)
        ((float4*)sWe)[i] = __ldg(((const float4*)W1e) + i);
    for (int i = threadIdx.x; i < HID * HID / 4; i += blockDim.x)
        ((float4*)sW2)[i] = __ldg(((const float4*)W2) + i);
    if (threadIdx.x < HID) sB2[threadIdx.x] = b2[threadIdx.x];
    __syncthreads();

    const int* srcp = ei;
    const int* dstp = ei + N_EDGES;

    for (int e = blockIdx.x * blockDim.x + threadIdx.x; e < N_EDGES;
         e += gridDim.x * blockDim.x) {
        int s = srcp[e], d = dstp[e];
        const ulonglong2* psp = (const ulonglong2*)(g_ps + (size_t)s * HID);
        const ulonglong2* pdp = (const ulonglong2*)(g_pd + (size_t)d * HID);
        const float4*     eap = (const float4*)(ea + (size_t)e * EDIM);

        // ---- layer 1: h = ps[src] + pd[dst] + ea @ W1e  (b1 folded into ps)
        ull acc[HID / 2];
        #pragma unroll
        for (int j = 0; j < 16; j++) {
            ulonglong2 a = psp[j];
            ulonglong2 b = pdp[j];
            fadd2(a.x, b.x);
            fadd2(a.y, b.y);
            acc[2 * j]     = a.x;
            acc[2 * j + 1] = a.y;
        }
        #pragma unroll 1
        for (int k4 = 0; k4 < 4; k4++)
            accum4(acc, eap[k4], sWe + (4 * k4) * HID);

        // ---- silu in place
        #pragma unroll
        for (int j = 0; j < HID / 2; j++) {
            float lo, hi;
            unpack2(acc[j], lo, hi);
            acc[j] = pack_pair(silu_f(lo), silu_f(hi));
        }

        // ---- layer 2 in two 32-output halves, FULLY UNROLLED (no dyn reg idx)
        float* aggp = g_agg + (size_t)d * HID;
        #pragma unroll 1
        for (int h = 0; h < 2; h++) {
            const float* w2h = sW2 + h * 32;
            ull acc2[16];
            #pragma unroll
            for (int j = 0; j < 16; j++)
                acc2[j] = ((const ull*)sB2)[h * 16 + j];

            #pragma unroll
            for (int jp = 0; jp < HID / 2; jp++) {
                float lo, hi;
                unpack2(acc[jp], lo, hi);
                accum_half(acc2, pack2(lo), w2h + (2 * jp) * HID);
                accum_half(acc2, pack2(hi), w2h + (2 * jp + 1) * HID);
            }

            #pragma unroll
            for (int j = 0; j < 8; j++) {
                float a0, a1, a2, a3;
                unpack2(acc2[2 * j],     a0, a1);
                unpack2(acc2[2 * j + 1], a2, a3);
                red_add4(aggp + h * 32 + 4 * j,
                         silu_f(a0), silu_f(a1), silu_f(a2), silu_f(a3));
            }
        }
    }
}

// ---------- 3) node MLP ----------
#define NODE_SMEM ((2 * HID * HID + HID) * 4)  // 33 KB

__global__ void __launch_bounds__(128, 4) node_kernel(
    const float* __restrict__ x,
    const float* __restrict__ W3, const float* __restrict__ b3,
    float* __restrict__ out)
{
    extern __shared__ float sm[];
    float* sW3 = sm;
    float* sB3 = sm + 2 * HID * HID;

    for (int i = threadIdx.x; i < 2 * HID * HID / 4; i += blockDim.x)
        ((float4*)sW3)[i] = __ldg(((const float4*)W3) + i);
    if (threadIdx.x < HID) sB3[threadIdx.x] = b3[threadIdx.x];
    __syncthreads();

    int n = blockIdx.x * blockDim.x + threadIdx.x;
    if (n >= N_NODES) return;

    const float4* xr = (const float4*)(x     + (size_t)n * HID);
    const float4* ar = (const float4*)(g_agg + (size_t)n * HID);

    ull acc[HID / 2];
    #pragma unroll
    for (int j = 0; j < HID / 2; j++) acc[j] = ((const ull*)sB3)[j];

    #pragma unroll 1
    for (int k4 = 0; k4 < 16; k4++)
        accum4(acc, xr[k4], sW3 + (4 * k4) * HID);
    #pragma unroll 1
    for (int k4 = 0; k4 < 16; k4++)
        accum4(acc, ar[k4], sW3 + (64 + 4 * k4) * HID);

    float4* op = (float4*)(out + (size_t)n * HID);
    #pragma unroll
    for (int j = 0; j < 16; j++) {
        float a0, a1, a2, a3;
        unpack2(acc[2 * j],     a0, a1);
        unpack2(acc[2 * j + 1], a2, a3);
        op[j] = make_float4(silu_f(a0), silu_f(a1), silu_f(a2), silu_f(a3));
    }
}

// ---------- 4) zero agg for the NEXT call ----------
__global__ void zero_agg_kernel() {
    size_t i = (size_t)blockIdx.x * blockDim.x + threadIdx.x;
    size_t n = (size_t)N_NODES * HID / 4;
    if (i < n) ((float4*)g_agg)[i] = make_float4(0.f, 0.f, 0.f, 0.f);
}

extern "C" void kernel_launch(void* const* d_in, const int* in_sizes, int n_in,
                              void* d_out, int out_size) {
    const float* x   = (const float*)d_in[0];
    const int*   ei  = (const int*)  d_in[1];
    const float* ea  = (const float*)d_in[2];
    const float* W1  = (const float*)d_in[3];
    const float* b1  = (const float*)d_in[4];
    const float* W2  = (const float*)d_in[5];
    const float* b2  = (const float*)d_in[6];
    const float* W3  = (const float*)d_in[7];
    const float* b3  = (const float*)d_in[8];
    float* out = (float*)d_out;

    // launch order has period 4 -> ncu's profiled launch #6 == edge_kernel
    int pgrid = (N_NODES + 127) / 128;
    proj_kernel<<<pgrid, 128, PROJ_SMEM>>>(x, W1, b1);

    edge_kernel<<<444, 128, EDGE_SMEM>>>(ei, ea, W1, b2, W2);

    node_kernel<<<pgrid, 128, NODE_SMEM>>>(x, W3, b3, out);

    int zgrid = (N_NODES * HID / 4 + 255) / 256;
    zero_agg_kernel<<<zgrid, 256>>>();   // leaves g_agg zeroed for next call
}